// round 1
// baseline (speedup 1.0000x reference)
#include <cuda_runtime.h>
#include <math.h>

#define BATCH 2
#define TSEQ  2048
#define CDIM  768
#define NH    12
#define HD    64

// Scratch (allocation-free rule: __device__ globals)
__device__ float g_qkv[(size_t)BATCH * TSEQ * 3 * CDIM];   // [B*T, 3C]
__device__ float g_att[(size_t)BATCH * TSEQ * CDIM];       // [B*T, C] (b,t,h,d merged)

// ---------------------------------------------------------------------------
// GEMM: C[m][n] = sum_k A[m][k] * W[n][k]   (A: [M,K] row-major, W: [N,K])
// 64x64x16 block tile, 16x16 threads, 4x4 per thread.
// ---------------------------------------------------------------------------
__global__ void gemm_nt_kernel(const float* __restrict__ A,
                               const float* __restrict__ W,
                               float* __restrict__ C,
                               int M, int N, int K) {
    __shared__ float As[16][64];
    __shared__ float Bs[16][64];

    const int tx = threadIdx.x, ty = threadIdx.y;
    const int tid = ty * 16 + tx;
    const int m0 = blockIdx.y * 64;
    const int n0 = blockIdx.x * 64;

    float acc[4][4] = {};

    const int lrow = tid >> 2;        // 0..63
    const int lkc  = (tid & 3) * 4;   // 0,4,8,12

    for (int k0 = 0; k0 < K; k0 += 16) {
        float4 va = *reinterpret_cast<const float4*>(&A[(size_t)(m0 + lrow) * K + k0 + lkc]);
        As[lkc + 0][lrow] = va.x; As[lkc + 1][lrow] = va.y;
        As[lkc + 2][lrow] = va.z; As[lkc + 3][lrow] = va.w;
        float4 vb = *reinterpret_cast<const float4*>(&W[(size_t)(n0 + lrow) * K + k0 + lkc]);
        Bs[lkc + 0][lrow] = vb.x; Bs[lkc + 1][lrow] = vb.y;
        Bs[lkc + 2][lrow] = vb.z; Bs[lkc + 3][lrow] = vb.w;
        __syncthreads();

#pragma unroll
        for (int kk = 0; kk < 16; kk++) {
            float4 a4 = *reinterpret_cast<const float4*>(&As[kk][ty * 4]);
            float4 b4 = *reinterpret_cast<const float4*>(&Bs[kk][tx * 4]);
            float av[4] = {a4.x, a4.y, a4.z, a4.w};
            float bv[4] = {b4.x, b4.y, b4.z, b4.w};
#pragma unroll
            for (int i = 0; i < 4; i++)
#pragma unroll
                for (int j = 0; j < 4; j++)
                    acc[i][j] = fmaf(av[i], bv[j], acc[i][j]);
        }
        __syncthreads();
    }

#pragma unroll
    for (int i = 0; i < 4; i++) {
        float4 o = make_float4(acc[i][0], acc[i][1], acc[i][2], acc[i][3]);
        *reinterpret_cast<float4*>(&C[(size_t)(m0 + ty * 4 + i) * N + n0 + tx * 4]) = o;
    }
}

// ---------------------------------------------------------------------------
// Flash attention (causal), fp32. One CTA per (q-tile of 64 rows, b*h).
// Smem: Qs[64][65], KP[64][65] (K tile, reused for P), Vs[64][64].
// ---------------------------------------------------------------------------
#define QS_STRIDE 65
#define SMEM_FLASH ((2 * 64 * 65 + 64 * 64) * 4)

__global__ void flash_attn_kernel(const float* __restrict__ qkv,
                                  float* __restrict__ out) {
    extern __shared__ float sm[];
    float* Qs = sm;                 // 64*65
    float* KP = sm + 64 * 65;       // 64*65 (K tile, then P tile)
    float* Vs = sm + 2 * 64 * 65;   // 64*64

    const int tx = threadIdx.x, ty = threadIdx.y;
    const int tid = ty * 16 + tx;
    const int qtile = blockIdx.x;
    const int bh = blockIdx.y;
    const int b = bh / NH, h = bh % NH;

    const size_t rs = 3 * CDIM;  // row stride in qkv
    const float* qb = qkv + (size_t)b * TSEQ * rs + (size_t)h * HD;
    const float* kb = qb + CDIM;
    const float* vb = qb + 2 * CDIM;

    // Load + scale Q tile (64 rows x 64 cols)
    for (int i = tid; i < 64 * 16; i += 256) {
        int r = i >> 4, c4 = (i & 15) * 4;
        float4 v = *reinterpret_cast<const float4*>(&qb[(size_t)(qtile * 64 + r) * rs + c4]);
        float* dst = &Qs[r * QS_STRIDE + c4];
        dst[0] = v.x * 0.125f; dst[1] = v.y * 0.125f;
        dst[2] = v.z * 0.125f; dst[3] = v.w * 0.125f;
    }

    float acc[4][4] = {};
    float mrow[4] = {-1e30f, -1e30f, -1e30f, -1e30f};
    float lrow[4] = {};

    for (int kt = 0; kt <= qtile; kt++) {
        __syncthreads();  // Q ready (iter 0) / previous PV consumers done
        for (int i = tid; i < 64 * 16; i += 256) {
            int r = i >> 4, c4 = (i & 15) * 4;
            float4 k4 = *reinterpret_cast<const float4*>(&kb[(size_t)(kt * 64 + r) * rs + c4]);
            float* kd = &KP[r * QS_STRIDE + c4];
            kd[0] = k4.x; kd[1] = k4.y; kd[2] = k4.z; kd[3] = k4.w;
            float4 v4 = *reinterpret_cast<const float4*>(&vb[(size_t)(kt * 64 + r) * rs + c4]);
            float* vd = &Vs[r * 64 + c4];
            vd[0] = v4.x; vd[1] = v4.y; vd[2] = v4.z; vd[3] = v4.w;
        }
        __syncthreads();

        // S = Q K^T (4x4 per thread)
        float s[4][4] = {};
#pragma unroll 8
        for (int d = 0; d < 64; d++) {
            float av[4], bv[4];
#pragma unroll
            for (int i = 0; i < 4; i++) av[i] = Qs[(ty * 4 + i) * QS_STRIDE + d];
#pragma unroll
            for (int j = 0; j < 4; j++) bv[j] = KP[(tx * 4 + j) * QS_STRIDE + d];
#pragma unroll
            for (int i = 0; i < 4; i++)
#pragma unroll
                for (int j = 0; j < 4; j++)
                    s[i][j] = fmaf(av[i], bv[j], s[i][j]);
        }

        // Causal mask on the diagonal tile
        if (kt == qtile) {
#pragma unroll
            for (int i = 0; i < 4; i++) {
                int iq = qtile * 64 + ty * 4 + i;
#pragma unroll
                for (int j = 0; j < 4; j++) {
                    int jk = kt * 64 + tx * 4 + j;
                    if (jk > iq) s[i][j] = -1e30f;
                }
            }
        }

        // Online softmax update (row reductions across the 16 tx lanes)
#pragma unroll
        for (int i = 0; i < 4; i++) {
            float mloc = fmaxf(fmaxf(s[i][0], s[i][1]), fmaxf(s[i][2], s[i][3]));
#pragma unroll
            for (int off = 1; off < 16; off <<= 1)
                mloc = fmaxf(mloc, __shfl_xor_sync(0xffffffffu, mloc, off));
            float mnew = fmaxf(mrow[i], mloc);
            float alpha = __expf(mrow[i] - mnew);
            float rsum = 0.f;
#pragma unroll
            for (int j = 0; j < 4; j++) {
                s[i][j] = __expf(s[i][j] - mnew);
                rsum += s[i][j];
            }
#pragma unroll
            for (int off = 1; off < 16; off <<= 1)
                rsum += __shfl_xor_sync(0xffffffffu, rsum, off);
            lrow[i] = lrow[i] * alpha + rsum;
            mrow[i] = mnew;
#pragma unroll
            for (int j = 0; j < 4; j++) acc[i][j] *= alpha;
        }

        __syncthreads();  // everyone done reading K tile
        // Write P over K tile
#pragma unroll
        for (int i = 0; i < 4; i++)
#pragma unroll
            for (int j = 0; j < 4; j++)
                KP[(ty * 4 + i) * QS_STRIDE + tx * 4 + j] = s[i][j];
        __syncthreads();

        // O += P V
#pragma unroll 8
        for (int k = 0; k < 64; k++) {
            float pv[4], vv[4];
#pragma unroll
            for (int i = 0; i < 4; i++) pv[i] = KP[(ty * 4 + i) * QS_STRIDE + k];
#pragma unroll
            for (int j = 0; j < 4; j++) vv[j] = Vs[k * 64 + tx * 4 + j];
#pragma unroll
            for (int i = 0; i < 4; i++)
#pragma unroll
                for (int j = 0; j < 4; j++)
                    acc[i][j] = fmaf(pv[i], vv[j], acc[i][j]);
        }
    }

    // Epilogue: normalize and store to [b, t, h*64 + d]
#pragma unroll
    for (int i = 0; i < 4; i++) {
        float inv = 1.0f / lrow[i];
        int iq = qtile * 64 + ty * 4 + i;
        float4 o = make_float4(acc[i][0] * inv, acc[i][1] * inv,
                               acc[i][2] * inv, acc[i][3] * inv);
        *reinterpret_cast<float4*>(
            &out[((size_t)b * TSEQ + iq) * CDIM + h * HD + tx * 4]) = o;
    }
}

// ---------------------------------------------------------------------------
extern "C" void kernel_launch(void* const* d_in, const int* in_sizes, int n_in,
                              void* d_out, int out_size) {
    const float* x      = (const float*)d_in[0];  // [B,T,C]
    const float* W_attn = (const float*)d_in[1];  // [3C, C]
    const float* W_proj = (const float*)d_in[2];  // [C, C]
    float* out = (float*)d_out;                   // [B,T,C]

    float* qkv = nullptr;
    float* att = nullptr;
    cudaGetSymbolAddress((void**)&qkv, g_qkv);
    cudaGetSymbolAddress((void**)&att, g_att);

    cudaFuncSetAttribute(flash_attn_kernel,
                         cudaFuncAttributeMaxDynamicSharedMemorySize, SMEM_FLASH);

    dim3 blk(16, 16);

    // 1) QKV projection: [4096,768] x [2304,768]^T -> [4096,2304]
    {
        dim3 grid((3 * CDIM) / 64, (BATCH * TSEQ) / 64);
        gemm_nt_kernel<<<grid, blk>>>(x, W_attn, qkv, BATCH * TSEQ, 3 * CDIM, CDIM);
    }

    // 2) Flash attention
    {
        dim3 grid(TSEQ / 64, BATCH * NH);
        flash_attn_kernel<<<grid, blk, SMEM_FLASH>>>(qkv, att);
    }

    // 3) Output projection: [4096,768] x [768,768]^T -> [4096,768]
    {
        dim3 grid(CDIM / 64, (BATCH * TSEQ) / 64);
        gemm_nt_kernel<<<grid, blk>>>(att, W_proj, out, BATCH * TSEQ, CDIM, CDIM);
    }
}

// round 5
// speedup vs baseline: 1.3267x; 1.3267x over previous
#include <cuda_runtime.h>
#include <cstdint>
#include <math.h>

#define BATCH 2
#define TSEQ  2048
#define CDIM  768
#define NH    12
#define HD    64

// Scratch (allocation-free rule: __device__ globals)
__device__ float g_qkv[(size_t)BATCH * TSEQ * 3 * CDIM];   // [B*T, 3C]
__device__ float g_att[(size_t)BATCH * TSEQ * CDIM];       // [B*T, C] (b,t,h,d merged)

__device__ __forceinline__ float to_tf32(float x) {
    uint32_t r;
    asm("cvt.rna.tf32.f32 %0, %1;" : "=r"(r) : "f"(x));
    return __uint_as_float(r);
}

__device__ __forceinline__ void mma_tf32(float c[4],
                                         uint32_t a0, uint32_t a1, uint32_t a2, uint32_t a3,
                                         uint32_t b0, uint32_t b1) {
    asm volatile(
        "mma.sync.aligned.m16n8k8.row.col.f32.tf32.tf32.f32 "
        "{%0,%1,%2,%3}, {%4,%5,%6,%7}, {%8,%9}, {%0,%1,%2,%3};"
        : "+f"(c[0]), "+f"(c[1]), "+f"(c[2]), "+f"(c[3])
        : "r"(a0), "r"(a1), "r"(a2), "r"(a3), "r"(b0), "r"(b1));
}

// ===========================================================================
// tf32 mma.sync GEMM: C[m][n] = sum_k A[m][k] * W[n][k]
// CTA 128x128, K-chunk 32. 8 warps: (wm = wid&3)*32 rows, (wn = wid>>2)*64 cols.
// Warp tile 32x64 = 2 mtiles (m16) x 8 ntiles (n8).
// Error-compensated: D += AhBh + AlBh + AhBl.
// ===========================================================================
#define GSTR 36   // smem row stride in floats (conflict-free: bank = 4g+t)
#define GEMM_SMEM (4 * 128 * GSTR * 4)   // sAh sAl sBh sBl = 73728 B

__global__ void __launch_bounds__(256, 2)
gemm_mma_kernel(const float* __restrict__ A,
                const float* __restrict__ W,
                float* __restrict__ C,
                int M, int N, int K) {
    extern __shared__ float sm[];
    float* sAh = sm;
    float* sAl = sm + 128 * GSTR;
    float* sBh = sm + 2 * 128 * GSTR;
    float* sBl = sm + 3 * 128 * GSTR;

    const int tid = threadIdx.x;
    const int wid = tid >> 5;
    const int lane = tid & 31;
    const int g = lane >> 2;      // 0..7
    const int t = lane & 3;       // 0..3
    const int wm = wid & 3;       // M quadrant (32 rows each)
    const int wn = wid >> 2;      // N half (64 cols each)
    const int m0 = blockIdx.y * 128;
    const int n0 = blockIdx.x * 128;

    float c[2][8][4];
#pragma unroll
    for (int i = 0; i < 2; i++)
#pragma unroll
        for (int j = 0; j < 8; j++)
#pragma unroll
            for (int q = 0; q < 4; q++) c[i][j][q] = 0.f;

    const int NIT = K / 32;
    for (int it = 0; it < NIT; it++) {
        const int k0 = it * 32;
        __syncthreads();  // previous compute done before overwriting smem

        // Stage A and B tiles (128 rows x 32 floats each), hi/lo split.
#pragma unroll
        for (int tt = 0; tt < 4; tt++) {
            int idx = tid + tt * 256;          // 0..1023
            int r = idx >> 3;                  // 0..127
            int c4 = (idx & 7) * 4;            // 0,4,...,28
            float4 va = *reinterpret_cast<const float4*>(&A[(size_t)(m0 + r) * K + k0 + c4]);
            float4 h, l;
            h.x = to_tf32(va.x); l.x = va.x - h.x;
            h.y = to_tf32(va.y); l.y = va.y - h.y;
            h.z = to_tf32(va.z); l.z = va.z - h.z;
            h.w = to_tf32(va.w); l.w = va.w - h.w;
            *reinterpret_cast<float4*>(&sAh[r * GSTR + c4]) = h;
            *reinterpret_cast<float4*>(&sAl[r * GSTR + c4]) = l;
            float4 vb = *reinterpret_cast<const float4*>(&W[(size_t)(n0 + r) * K + k0 + c4]);
            h.x = to_tf32(vb.x); l.x = vb.x - h.x;
            h.y = to_tf32(vb.y); l.y = vb.y - h.y;
            h.z = to_tf32(vb.z); l.z = vb.z - h.z;
            h.w = to_tf32(vb.w); l.w = vb.w - h.w;
            *reinterpret_cast<float4*>(&sBh[r * GSTR + c4]) = h;
            *reinterpret_cast<float4*>(&sBl[r * GSTR + c4]) = l;
        }
        __syncthreads();

        // 4 k-steps of 8
#pragma unroll
        for (int ks = 0; ks < 4; ks++) {
            const int kk = ks * 8;
            // A fragments for both mtiles (hi & lo)
            uint32_t ah[2][4], al[2][4];
#pragma unroll
            for (int mt = 0; mt < 2; mt++) {
                int mrow = wm * 32 + mt * 16;
                const float* pah = &sAh[(mrow + g) * GSTR + kk + t];
                const float* pal = &sAl[(mrow + g) * GSTR + kk + t];
                ah[mt][0] = __float_as_uint(pah[0]);
                ah[mt][1] = __float_as_uint(pah[8 * GSTR]);
                ah[mt][2] = __float_as_uint(pah[4]);
                ah[mt][3] = __float_as_uint(pah[8 * GSTR + 4]);
                al[mt][0] = __float_as_uint(pal[0]);
                al[mt][1] = __float_as_uint(pal[8 * GSTR]);
                al[mt][2] = __float_as_uint(pal[4]);
                al[mt][3] = __float_as_uint(pal[8 * GSTR + 4]);
            }
#pragma unroll
            for (int nt = 0; nt < 8; nt++) {
                int ncol = wn * 64 + nt * 8;
                const float* pbh = &sBh[(ncol + g) * GSTR + kk + t];
                const float* pbl = &sBl[(ncol + g) * GSTR + kk + t];
                uint32_t b0h = __float_as_uint(pbh[0]);
                uint32_t b1h = __float_as_uint(pbh[4]);
                uint32_t b0l = __float_as_uint(pbl[0]);
                uint32_t b1l = __float_as_uint(pbl[4]);
#pragma unroll
                for (int mt = 0; mt < 2; mt++) {
                    mma_tf32(c[mt][nt], ah[mt][0], ah[mt][1], ah[mt][2], ah[mt][3], b0h, b1h);
                    mma_tf32(c[mt][nt], al[mt][0], al[mt][1], al[mt][2], al[mt][3], b0h, b1h);
                    mma_tf32(c[mt][nt], ah[mt][0], ah[mt][1], ah[mt][2], ah[mt][3], b0l, b1l);
                }
            }
        }
    }

    // Epilogue: c0,c1 -> (row, col..col+1); c2,c3 -> (row+8, ...)
#pragma unroll
    for (int mt = 0; mt < 2; mt++) {
        int row = m0 + wm * 32 + mt * 16 + g;
#pragma unroll
        for (int nt = 0; nt < 8; nt++) {
            int col = n0 + wn * 64 + nt * 8 + 2 * t;
            *reinterpret_cast<float2*>(&C[(size_t)row * N + col]) =
                make_float2(c[mt][nt][0], c[mt][nt][1]);
            *reinterpret_cast<float2*>(&C[(size_t)(row + 8) * N + col]) =
                make_float2(c[mt][nt][2], c[mt][nt][3]);
        }
    }
}

// ---------------------------------------------------------------------------
// Flash attention (causal), fp32. One CTA per (q-tile of 64 rows, b*h).
// (unchanged from round 1)
// ---------------------------------------------------------------------------
#define QS_STRIDE 65
#define SMEM_FLASH ((2 * 64 * 65 + 64 * 64) * 4)

__global__ void flash_attn_kernel(const float* __restrict__ qkv,
                                  float* __restrict__ out) {
    extern __shared__ float smf[];
    float* Qs = smf;                 // 64*65
    float* KP = smf + 64 * 65;       // 64*65 (K tile, then P tile)
    float* Vs = smf + 2 * 64 * 65;   // 64*64

    const int tx = threadIdx.x, ty = threadIdx.y;
    const int tid = ty * 16 + tx;
    const int qtile = blockIdx.x;
    const int bh = blockIdx.y;
    const int b = bh / NH, h = bh % NH;

    const size_t rs = 3 * CDIM;
    const float* qb = qkv + (size_t)b * TSEQ * rs + (size_t)h * HD;
    const float* kb = qb + CDIM;
    const float* vb = qb + 2 * CDIM;

    for (int i = tid; i < 64 * 16; i += 256) {
        int r = i >> 4, c4 = (i & 15) * 4;
        float4 v = *reinterpret_cast<const float4*>(&qb[(size_t)(qtile * 64 + r) * rs + c4]);
        float* dst = &Qs[r * QS_STRIDE + c4];
        dst[0] = v.x * 0.125f; dst[1] = v.y * 0.125f;
        dst[2] = v.z * 0.125f; dst[3] = v.w * 0.125f;
    }

    float acc[4][4] = {};
    float mrow[4] = {-1e30f, -1e30f, -1e30f, -1e30f};
    float lrow[4] = {};

    for (int kt = 0; kt <= qtile; kt++) {
        __syncthreads();
        for (int i = tid; i < 64 * 16; i += 256) {
            int r = i >> 4, c4 = (i & 15) * 4;
            float4 k4 = *reinterpret_cast<const float4*>(&kb[(size_t)(kt * 64 + r) * rs + c4]);
            float* kd = &KP[r * QS_STRIDE + c4];
            kd[0] = k4.x; kd[1] = k4.y; kd[2] = k4.z; kd[3] = k4.w;
            float4 v4 = *reinterpret_cast<const float4*>(&vb[(size_t)(kt * 64 + r) * rs + c4]);
            float* vd = &Vs[r * 64 + c4];
            vd[0] = v4.x; vd[1] = v4.y; vd[2] = v4.z; vd[3] = v4.w;
        }
        __syncthreads();

        float s[4][4] = {};
#pragma unroll 8
        for (int d = 0; d < 64; d++) {
            float av[4], bv[4];
#pragma unroll
            for (int i = 0; i < 4; i++) av[i] = Qs[(ty * 4 + i) * QS_STRIDE + d];
#pragma unroll
            for (int j = 0; j < 4; j++) bv[j] = KP[(tx * 4 + j) * QS_STRIDE + d];
#pragma unroll
            for (int i = 0; i < 4; i++)
#pragma unroll
                for (int j = 0; j < 4; j++)
                    s[i][j] = fmaf(av[i], bv[j], s[i][j]);
        }

        if (kt == qtile) {
#pragma unroll
            for (int i = 0; i < 4; i++) {
                int iq = qtile * 64 + ty * 4 + i;
#pragma unroll
                for (int j = 0; j < 4; j++) {
                    int jk = kt * 64 + tx * 4 + j;
                    if (jk > iq) s[i][j] = -1e30f;
                }
            }
        }

#pragma unroll
        for (int i = 0; i < 4; i++) {
            float mloc = fmaxf(fmaxf(s[i][0], s[i][1]), fmaxf(s[i][2], s[i][3]));
#pragma unroll
            for (int off = 1; off < 16; off <<= 1)
                mloc = fmaxf(mloc, __shfl_xor_sync(0xffffffffu, mloc, off));
            float mnew = fmaxf(mrow[i], mloc);
            float alpha = __expf(mrow[i] - mnew);
            float rsum = 0.f;
#pragma unroll
            for (int j = 0; j < 4; j++) {
                s[i][j] = __expf(s[i][j] - mnew);
                rsum += s[i][j];
            }
#pragma unroll
            for (int off = 1; off < 16; off <<= 1)
                rsum += __shfl_xor_sync(0xffffffffu, rsum, off);
            lrow[i] = lrow[i] * alpha + rsum;
            mrow[i] = mnew;
#pragma unroll
            for (int j = 0; j < 4; j++) acc[i][j] *= alpha;
        }

        __syncthreads();
#pragma unroll
        for (int i = 0; i < 4; i++)
#pragma unroll
            for (int j = 0; j < 4; j++)
                KP[(ty * 4 + i) * QS_STRIDE + tx * 4 + j] = s[i][j];
        __syncthreads();

#pragma unroll 8
        for (int k = 0; k < 64; k++) {
            float pv[4], vv[4];
#pragma unroll
            for (int i = 0; i < 4; i++) pv[i] = KP[(ty * 4 + i) * QS_STRIDE + k];
#pragma unroll
            for (int j = 0; j < 4; j++) vv[j] = Vs[k * 64 + tx * 4 + j];
#pragma unroll
            for (int i = 0; i < 4; i++)
#pragma unroll
                for (int j = 0; j < 4; j++)
                    acc[i][j] = fmaf(pv[i], vv[j], acc[i][j]);
        }
    }

#pragma unroll
    for (int i = 0; i < 4; i++) {
        float inv = 1.0f / lrow[i];
        int iq = qtile * 64 + ty * 4 + i;
        float4 o = make_float4(acc[i][0] * inv, acc[i][1] * inv,
                               acc[i][2] * inv, acc[i][3] * inv);
        *reinterpret_cast<float4*>(
            &out[((size_t)b * TSEQ + iq) * CDIM + h * HD + tx * 4]) = o;
    }
}

// ---------------------------------------------------------------------------
extern "C" void kernel_launch(void* const* d_in, const int* in_sizes, int n_in,
                              void* d_out, int out_size) {
    const float* x      = (const float*)d_in[0];  // [B,T,C]
    const float* W_attn = (const float*)d_in[1];  // [3C, C]
    const float* W_proj = (const float*)d_in[2];  // [C, C]
    float* out = (float*)d_out;                   // [B,T,C]

    float* qkv = nullptr;
    float* att = nullptr;
    cudaGetSymbolAddress((void**)&qkv, g_qkv);
    cudaGetSymbolAddress((void**)&att, g_att);

    cudaFuncSetAttribute(gemm_mma_kernel,
                         cudaFuncAttributeMaxDynamicSharedMemorySize, GEMM_SMEM);
    cudaFuncSetAttribute(flash_attn_kernel,
                         cudaFuncAttributeMaxDynamicSharedMemorySize, SMEM_FLASH);

    // 1) QKV projection: [4096,768] x [2304,768]^T -> [4096,2304]
    {
        dim3 grid((3 * CDIM) / 128, (BATCH * TSEQ) / 128);
        gemm_mma_kernel<<<grid, 256, GEMM_SMEM>>>(x, W_attn, qkv, BATCH * TSEQ, 3 * CDIM, CDIM);
    }

    // 2) Flash attention
    {
        dim3 blk(16, 16);
        dim3 grid(TSEQ / 64, BATCH * NH);
        flash_attn_kernel<<<grid, blk, SMEM_FLASH>>>(qkv, att);
    }

    // 3) Output projection: [4096,768] x [768,768]^T -> [4096,768]
    {
        dim3 grid(CDIM / 128, (BATCH * TSEQ) / 128);
        gemm_mma_kernel<<<grid, 256, GEMM_SMEM>>>(att, W_proj, out, BATCH * TSEQ, CDIM, CDIM);
    }
}

// round 6
// speedup vs baseline: 1.3365x; 1.0074x over previous
#include <cuda_runtime.h>
#include <cstdint>
#include <math.h>

#define BATCH 2
#define TSEQ  2048
#define CDIM  768
#define NH    12
#define HD    64

// Scratch (allocation-free rule: __device__ globals)
__device__ float g_qkv[(size_t)BATCH * TSEQ * 3 * CDIM];   // [B*T, 3C]
__device__ float g_att[(size_t)BATCH * TSEQ * CDIM];       // [B*T, C] (b,t,h,d merged)

__device__ __forceinline__ float to_tf32(float x) {
    uint32_t r;
    asm("cvt.rna.tf32.f32 %0, %1;" : "=r"(r) : "f"(x));
    return __uint_as_float(r);
}

__device__ __forceinline__ void mma_tf32(float c[4],
                                         uint32_t a0, uint32_t a1, uint32_t a2, uint32_t a3,
                                         uint32_t b0, uint32_t b1) {
    asm volatile(
        "mma.sync.aligned.m16n8k8.row.col.f32.tf32.tf32.f32 "
        "{%0,%1,%2,%3}, {%4,%5,%6,%7}, {%8,%9}, {%0,%1,%2,%3};"
        : "+f"(c[0]), "+f"(c[1]), "+f"(c[2]), "+f"(c[3])
        : "r"(a0), "r"(a1), "r"(a2), "r"(a3), "r"(b0), "r"(b1));
}

// ===========================================================================
// tf32 mma.sync GEMM: C[m][n] = sum_k A[m][k] * W[n][k]
// CTA 128x128, K-chunk 32. 8 warps: (wm = wid&3)*32 rows, (wn = wid>>2)*64 cols.
// Warp tile 32x64 = 2 mtiles (m16) x 8 ntiles (n8).
// Error-compensated: D += AhBh + AlBh + AhBl.
// ===========================================================================
#define GSTR 36   // smem row stride in floats (conflict-free: bank = 4g+t)
#define GEMM_SMEM (4 * 128 * GSTR * 4)   // sAh sAl sBh sBl = 73728 B

__global__ void __launch_bounds__(256, 2)
gemm_mma_kernel(const float* __restrict__ A,
                const float* __restrict__ W,
                float* __restrict__ C,
                int M, int N, int K) {
    extern __shared__ float sm[];
    float* sAh = sm;
    float* sAl = sm + 128 * GSTR;
    float* sBh = sm + 2 * 128 * GSTR;
    float* sBl = sm + 3 * 128 * GSTR;

    const int tid = threadIdx.x;
    const int wid = tid >> 5;
    const int lane = tid & 31;
    const int g = lane >> 2;      // 0..7
    const int t = lane & 3;       // 0..3
    const int wm = wid & 3;       // M quadrant (32 rows each)
    const int wn = wid >> 2;      // N half (64 cols each)
    const int m0 = blockIdx.y * 128;
    const int n0 = blockIdx.x * 128;

    float c[2][8][4];
#pragma unroll
    for (int i = 0; i < 2; i++)
#pragma unroll
        for (int j = 0; j < 8; j++)
#pragma unroll
            for (int q = 0; q < 4; q++) c[i][j][q] = 0.f;

    const int NIT = K / 32;
    for (int it = 0; it < NIT; it++) {
        const int k0 = it * 32;
        __syncthreads();  // previous compute done before overwriting smem

        // Stage A and B tiles (128 rows x 32 floats each), hi/lo split.
#pragma unroll
        for (int tt = 0; tt < 4; tt++) {
            int idx = tid + tt * 256;          // 0..1023
            int r = idx >> 3;                  // 0..127
            int c4 = (idx & 7) * 4;            // 0,4,...,28
            float4 va = *reinterpret_cast<const float4*>(&A[(size_t)(m0 + r) * K + k0 + c4]);
            float4 h, l;
            h.x = to_tf32(va.x); l.x = va.x - h.x;
            h.y = to_tf32(va.y); l.y = va.y - h.y;
            h.z = to_tf32(va.z); l.z = va.z - h.z;
            h.w = to_tf32(va.w); l.w = va.w - h.w;
            *reinterpret_cast<float4*>(&sAh[r * GSTR + c4]) = h;
            *reinterpret_cast<float4*>(&sAl[r * GSTR + c4]) = l;
            float4 vb = *reinterpret_cast<const float4*>(&W[(size_t)(n0 + r) * K + k0 + c4]);
            h.x = to_tf32(vb.x); l.x = vb.x - h.x;
            h.y = to_tf32(vb.y); l.y = vb.y - h.y;
            h.z = to_tf32(vb.z); l.z = vb.z - h.z;
            h.w = to_tf32(vb.w); l.w = vb.w - h.w;
            *reinterpret_cast<float4*>(&sBh[r * GSTR + c4]) = h;
            *reinterpret_cast<float4*>(&sBl[r * GSTR + c4]) = l;
        }
        __syncthreads();

        // 4 k-steps of 8
#pragma unroll
        for (int ks = 0; ks < 4; ks++) {
            const int kk = ks * 8;
            // A fragments for both mtiles (hi & lo)
            uint32_t ah[2][4], al[2][4];
#pragma unroll
            for (int mt = 0; mt < 2; mt++) {
                int mrow = wm * 32 + mt * 16;
                const float* pah = &sAh[(mrow + g) * GSTR + kk + t];
                const float* pal = &sAl[(mrow + g) * GSTR + kk + t];
                ah[mt][0] = __float_as_uint(pah[0]);
                ah[mt][1] = __float_as_uint(pah[8 * GSTR]);
                ah[mt][2] = __float_as_uint(pah[4]);
                ah[mt][3] = __float_as_uint(pah[8 * GSTR + 4]);
                al[mt][0] = __float_as_uint(pal[0]);
                al[mt][1] = __float_as_uint(pal[8 * GSTR]);
                al[mt][2] = __float_as_uint(pal[4]);
                al[mt][3] = __float_as_uint(pal[8 * GSTR + 4]);
            }
#pragma unroll
            for (int nt = 0; nt < 8; nt++) {
                int ncol = wn * 64 + nt * 8;
                const float* pbh = &sBh[(ncol + g) * GSTR + kk + t];
                const float* pbl = &sBl[(ncol + g) * GSTR + kk + t];
                uint32_t b0h = __float_as_uint(pbh[0]);
                uint32_t b1h = __float_as_uint(pbh[4]);
                uint32_t b0l = __float_as_uint(pbl[0]);
                uint32_t b1l = __float_as_uint(pbl[4]);
#pragma unroll
                for (int mt = 0; mt < 2; mt++) {
                    mma_tf32(c[mt][nt], ah[mt][0], ah[mt][1], ah[mt][2], ah[mt][3], b0h, b1h);
                    mma_tf32(c[mt][nt], al[mt][0], al[mt][1], al[mt][2], al[mt][3], b0h, b1h);
                    mma_tf32(c[mt][nt], ah[mt][0], ah[mt][1], ah[mt][2], ah[mt][3], b0l, b1l);
                }
            }
        }
    }

    // Epilogue: c0,c1 -> (row, col..col+1); c2,c3 -> (row+8, ...)
#pragma unroll
    for (int mt = 0; mt < 2; mt++) {
        int row = m0 + wm * 32 + mt * 16 + g;
#pragma unroll
        for (int nt = 0; nt < 8; nt++) {
            int col = n0 + wn * 64 + nt * 8 + 2 * t;
            *reinterpret_cast<float2*>(&C[(size_t)row * N + col]) =
                make_float2(c[mt][nt][0], c[mt][nt][1]);
            *reinterpret_cast<float2*>(&C[(size_t)(row + 8) * N + col]) =
                make_float2(c[mt][nt][2], c[mt][nt][3]);
        }
    }
}

// ---------------------------------------------------------------------------
// Flash attention (causal), fp32. One CTA per (q-tile of 64 rows, b*h).
// (unchanged from round 1)
// ---------------------------------------------------------------------------
#define QS_STRIDE 65
#define SMEM_FLASH ((2 * 64 * 65 + 64 * 64) * 4)

__global__ void flash_attn_kernel(const float* __restrict__ qkv,
                                  float* __restrict__ out) {
    extern __shared__ float smf[];
    float* Qs = smf;                 // 64*65
    float* KP = smf + 64 * 65;       // 64*65 (K tile, then P tile)
    float* Vs = smf + 2 * 64 * 65;   // 64*64

    const int tx = threadIdx.x, ty = threadIdx.y;
    const int tid = ty * 16 + tx;
    const int qtile = blockIdx.x;
    const int bh = blockIdx.y;
    const int b = bh / NH, h = bh % NH;

    const size_t rs = 3 * CDIM;
    const float* qb = qkv + (size_t)b * TSEQ * rs + (size_t)h * HD;
    const float* kb = qb + CDIM;
    const float* vb = qb + 2 * CDIM;

    for (int i = tid; i < 64 * 16; i += 256) {
        int r = i >> 4, c4 = (i & 15) * 4;
        float4 v = *reinterpret_cast<const float4*>(&qb[(size_t)(qtile * 64 + r) * rs + c4]);
        float* dst = &Qs[r * QS_STRIDE + c4];
        dst[0] = v.x * 0.125f; dst[1] = v.y * 0.125f;
        dst[2] = v.z * 0.125f; dst[3] = v.w * 0.125f;
    }

    float acc[4][4] = {};
    float mrow[4] = {-1e30f, -1e30f, -1e30f, -1e30f};
    float lrow[4] = {};

    for (int kt = 0; kt <= qtile; kt++) {
        __syncthreads();
        for (int i = tid; i < 64 * 16; i += 256) {
            int r = i >> 4, c4 = (i & 15) * 4;
            float4 k4 = *reinterpret_cast<const float4*>(&kb[(size_t)(kt * 64 + r) * rs + c4]);
            float* kd = &KP[r * QS_STRIDE + c4];
            kd[0] = k4.x; kd[1] = k4.y; kd[2] = k4.z; kd[3] = k4.w;
            float4 v4 = *reinterpret_cast<const float4*>(&vb[(size_t)(kt * 64 + r) * rs + c4]);
            float* vd = &Vs[r * 64 + c4];
            vd[0] = v4.x; vd[1] = v4.y; vd[2] = v4.z; vd[3] = v4.w;
        }
        __syncthreads();

        float s[4][4] = {};
#pragma unroll 8
        for (int d = 0; d < 64; d++) {
            float av[4], bv[4];
#pragma unroll
            for (int i = 0; i < 4; i++) av[i] = Qs[(ty * 4 + i) * QS_STRIDE + d];
#pragma unroll
            for (int j = 0; j < 4; j++) bv[j] = KP[(tx * 4 + j) * QS_STRIDE + d];
#pragma unroll
            for (int i = 0; i < 4; i++)
#pragma unroll
                for (int j = 0; j < 4; j++)
                    s[i][j] = fmaf(av[i], bv[j], s[i][j]);
        }

        if (kt == qtile) {
#pragma unroll
            for (int i = 0; i < 4; i++) {
                int iq = qtile * 64 + ty * 4 + i;
#pragma unroll
                for (int j = 0; j < 4; j++) {
                    int jk = kt * 64 + tx * 4 + j;
                    if (jk > iq) s[i][j] = -1e30f;
                }
            }
        }

#pragma unroll
        for (int i = 0; i < 4; i++) {
            float mloc = fmaxf(fmaxf(s[i][0], s[i][1]), fmaxf(s[i][2], s[i][3]));
#pragma unroll
            for (int off = 1; off < 16; off <<= 1)
                mloc = fmaxf(mloc, __shfl_xor_sync(0xffffffffu, mloc, off));
            float mnew = fmaxf(mrow[i], mloc);
            float alpha = __expf(mrow[i] - mnew);
            float rsum = 0.f;
#pragma unroll
            for (int j = 0; j < 4; j++) {
                s[i][j] = __expf(s[i][j] - mnew);
                rsum += s[i][j];
            }
#pragma unroll
            for (int off = 1; off < 16; off <<= 1)
                rsum += __shfl_xor_sync(0xffffffffu, rsum, off);
            lrow[i] = lrow[i] * alpha + rsum;
            mrow[i] = mnew;
#pragma unroll
            for (int j = 0; j < 4; j++) acc[i][j] *= alpha;
        }

        __syncthreads();
#pragma unroll
        for (int i = 0; i < 4; i++)
#pragma unroll
            for (int j = 0; j < 4; j++)
                KP[(ty * 4 + i) * QS_STRIDE + tx * 4 + j] = s[i][j];
        __syncthreads();

#pragma unroll 8
        for (int k = 0; k < 64; k++) {
            float pv[4], vv[4];
#pragma unroll
            for (int i = 0; i < 4; i++) pv[i] = KP[(ty * 4 + i) * QS_STRIDE + k];
#pragma unroll
            for (int j = 0; j < 4; j++) vv[j] = Vs[k * 64 + tx * 4 + j];
#pragma unroll
            for (int i = 0; i < 4; i++)
#pragma unroll
                for (int j = 0; j < 4; j++)
                    acc[i][j] = fmaf(pv[i], vv[j], acc[i][j]);
        }
    }

#pragma unroll
    for (int i = 0; i < 4; i++) {
        float inv = 1.0f / lrow[i];
        int iq = qtile * 64 + ty * 4 + i;
        float4 o = make_float4(acc[i][0] * inv, acc[i][1] * inv,
                               acc[i][2] * inv, acc[i][3] * inv);
        *reinterpret_cast<float4*>(
            &out[((size_t)b * TSEQ + iq) * CDIM + h * HD + tx * 4]) = o;
    }
}

// ---------------------------------------------------------------------------
extern "C" void kernel_launch(void* const* d_in, const int* in_sizes, int n_in,
                              void* d_out, int out_size) {
    const float* x      = (const float*)d_in[0];  // [B,T,C]
    const float* W_attn = (const float*)d_in[1];  // [3C, C]
    const float* W_proj = (const float*)d_in[2];  // [C, C]
    float* out = (float*)d_out;                   // [B,T,C]

    float* qkv = nullptr;
    float* att = nullptr;
    cudaGetSymbolAddress((void**)&qkv, g_qkv);
    cudaGetSymbolAddress((void**)&att, g_att);

    cudaFuncSetAttribute(gemm_mma_kernel,
                         cudaFuncAttributeMaxDynamicSharedMemorySize, GEMM_SMEM);
    cudaFuncSetAttribute(flash_attn_kernel,
                         cudaFuncAttributeMaxDynamicSharedMemorySize, SMEM_FLASH);

    // 1) QKV projection: [4096,768] x [2304,768]^T -> [4096,2304]
    {
        dim3 grid((3 * CDIM) / 128, (BATCH * TSEQ) / 128);
        gemm_mma_kernel<<<grid, 256, GEMM_SMEM>>>(x, W_attn, qkv, BATCH * TSEQ, 3 * CDIM, CDIM);
    }

    // 2) Flash attention
    {
        dim3 blk(16, 16);
        dim3 grid(TSEQ / 64, BATCH * NH);
        flash_attn_kernel<<<grid, blk, SMEM_FLASH>>>(qkv, att);
    }

    // 3) Output projection: [4096,768] x [768,768]^T -> [4096,768]
    {
        dim3 grid(CDIM / 128, (BATCH * TSEQ) / 128);
        gemm_mma_kernel<<<grid, 256, GEMM_SMEM>>>(att, W_proj, out, BATCH * TSEQ, CDIM, CDIM);
    }
}